// round 17
// baseline (speedup 1.0000x reference)
#include <cuda_runtime.h>
#include <cuda_bf16.h>

// SENet gating, converged configuration:
//   - block-granular 21 KB cp.async.bulk load (evict_first), mbarrier wait
//   - R=7 rows/warp, 9 blocks/SM (regs<=56, smem ~24 KB)
//   - segment sums with SPLIT accumulators (half the FADD dependency depth)
//   - MLP 12->3->12 reading means from smem (low regs)
//   - gate-mul -> direct __stcs STG.128 to gmem, no drain

#define NFEAT 188
#define NF4   47
#define R     7                    // rows per warp
#define WARPS 4
#define NTHREADS (WARPS * 32)
#define ROWS_BLK (WARPS * R)       // 28
#define TILE_F  (ROWS_BLK * NFEAT) // 5264 floats = 21056 B

// packed segment ids for the 4 features of each float4 position (0..46)
__device__ __constant__ unsigned int c_stab[47] = {
    0x00000000u,0x00000000u,0x00000000u,0x00000000u,0x00000000u,
    0x01010101u,0x02020101u,0x02020202u,0x02020202u,0x02020202u,
    0x02020202u,0x03020202u,0x03030303u,0x03030303u,0x03030303u,
    0x03030303u,0x04030303u,0x04040404u,0x05050504u,0x05050505u,
    0x05050505u,0x05050505u,0x05050505u,0x06060505u,0x06060606u,
    0x06060606u,0x06060606u,0x06060606u,0x07070606u,0x07070707u,
    0x08080808u,0x08080808u,0x08080808u,0x08080808u,0x08080808u,
    0x09090908u,0x09090909u,0x09090909u,0x09090909u,0x09090909u,
    0x0A0A0A09u,0x0B0A0A0Au,0x0B0B0B0Bu,0x0B0B0B0Bu,0x0B0B0B0Bu,
    0x0B0B0B0Bu,0x0B0B0B0Bu
};

__global__ __launch_bounds__(NTHREADS, 9)
void senet_kernel(const float* __restrict__ x,
                  const float* __restrict__ W1,   // [3,12]
                  const float* __restrict__ b1,   // [3]
                  const float* __restrict__ W2,   // [12,3]
                  const float* __restrict__ b2,   // [12]
                  float* __restrict__ out,
                  int B)
{
    __shared__ __align__(16) float sx[TILE_F];              // 21056 B
    __shared__ __align__(8)  unsigned long long smbar;
    __shared__ float        smeans[WARPS][R][12];
    __shared__ float        sgates[WARPS][R][13];
    __shared__ float        sw[88];
    __shared__ unsigned int sstab[47];

    const int tid  = threadIdx.x;
    const int lane = tid & 31;
    const int w    = tid >> 5;

    const long long brow0 = (long long)blockIdx.x * ROWS_BLK;
    int rows_blk = B - (int)brow0;
    if (rows_blk > ROWS_BLK) rows_blk = ROWS_BLK;
    const unsigned int bytes = (unsigned int)(rows_blk * NFEAT) * 4u;

    const unsigned int sdst = (unsigned int)__cvta_generic_to_shared(sx);
    const unsigned int mb   = (unsigned int)__cvta_generic_to_shared(&smbar);
    const char* gsrc = (const char*)(x + brow0 * NFEAT);

    // ---- phase 0: init barrier, stage tables; ONE bulk load ----
    if (tid == 0) {
        asm volatile("mbarrier.init.shared.b64 [%0], 1;" :: "r"(mb) : "memory");
        asm volatile("fence.proxy.async.shared::cta;" ::: "memory");
        asm volatile("mbarrier.arrive.expect_tx.shared.b64 _, [%0], %1;"
                     :: "r"(mb), "r"(bytes) : "memory");
        asm volatile(
            "{\n\t.reg .b64 pol;\n\t"
            "createpolicy.fractional.L2::evict_first.b64 pol, 1.0;\n\t"
            "cp.async.bulk.shared::cluster.global.mbarrier::complete_tx::bytes.L2::cache_hint"
            " [%0], [%1], %2, [%3], pol;\n\t}"
            :: "r"(sdst), "l"(gsrc), "r"(bytes), "r"(mb) : "memory");
    }
    if (tid < 47) sstab[tid] = c_stab[tid];
    for (int j = tid; j < 87; j += NTHREADS) {
        float v;
        if      (j < 36) v = __ldg(W1 + j);
        else if (j < 39) v = __ldg(b1 + (j - 36));
        else if (j < 75) v = __ldg(W2 + (j - 39));
        else             v = __ldg(b2 + (j - 75));
        sw[j] = v;
    }
    __syncthreads();    // mbarrier.init + tables visible to all warps

    // ---- wait for tile (parity 0), every thread ----
    {
        unsigned int done;
        asm volatile(
            "{\n\t.reg .pred p;\n\t"
            "mbarrier.try_wait.parity.acquire.cta.shared::cta.b64 p, [%1], 0;\n\t"
            "selp.b32 %0, 1, 0, p;\n\t}"
            : "=r"(done) : "r"(mb) : "memory");
        if (!done) {
            asm volatile(
                "{\n\t.reg .pred p;\n"
                "W_%=:\n\t"
                "mbarrier.try_wait.parity.acquire.cta.shared::cta.b64 p, [%0], 0, 0x989680;\n\t"
                "@p bra D_%=;\n\t"
                "bra.uni W_%=;\n"
                "D_%=:\n\t}"
                :: "r"(mb) : "memory");
        }
    }
    __syncwarp();

    // per-warp row count / region
    int rows = rows_blk - w * R;
    if (rows < 0) rows = 0;
    if (rows > R) rows = R;
    float* sxw = sx + w * (R * NFEAT);

    if (rows > 0) {
        // ---- phase 2: segment sums, SPLIT accumulators (2x ILP) ----
        {
            const int rq = lane >> 2;       // 0..7; rq==7 idle (R=7)
            const int sq = lane & 3;
            if (rq < rows) {
                const float* xr = sxw + rq * NFEAT + sq * 47;
                // seg a: 20 elems -> two chains of 10
                float a0 = 0.f, a1 = 0.f;
                #pragma unroll
                for (int j = 0; j < 20; j += 2) { a0 += xr[j]; a1 += xr[j + 1]; }
                // seg b: 6 elems -> two chains of 3
                float b0 = 0.f, b1v = 0.f;
                #pragma unroll
                for (int j = 20; j < 26; j += 2) { b0 += xr[j]; b1v += xr[j + 1]; }
                // seg c: 21 elems -> two chains (11 + 10)
                float c0 = xr[46], c1 = 0.f;
                #pragma unroll
                for (int j = 26; j < 46; j += 2) { c0 += xr[j]; c1 += xr[j + 1]; }
                smeans[w][rq][3 * sq + 0] = (a0 + a1)  * (1.f / 20.f);
                smeans[w][rq][3 * sq + 1] = (b0 + b1v) * (1.f / 6.f);
                smeans[w][rq][3 * sq + 2] = (c0 + c1)  * (1.f / 21.f);
            }
        }
        __syncwarp();

        // ---- phase 3: tiny MLP, one lane per row (means read from smem) ----
        if (lane < rows) {
            const float* mp = smeans[w][lane];
            float h[3];
            #pragma unroll
            for (int j = 0; j < 3; ++j) {
                float a = sw[36 + j];
                #pragma unroll
                for (int k = 0; k < 12; ++k) a += mp[k] * sw[j * 12 + k];
                h[j] = fmaxf(a, 0.f);
            }
            #pragma unroll
            for (int s = 0; s < 12; ++s) {
                float a = sw[75 + s];
                #pragma unroll
                for (int j = 0; j < 3; ++j) a += h[j] * sw[39 + s * 3 + j];
                sgates[w][lane][s] = __fdividef(1.f, 1.f + __expf(-a));
            }
        }
        __syncwarp();

        // ---- phase 4: gate-mul -> DIRECT streaming store to gmem ----
        {
            const float4* sxw4 = (const float4*)sxw;
            float4* gout = (float4*)(out + (brow0 + w * R) * NFEAT);
            const int n4 = rows * NF4;
            #pragma unroll 3
            for (int i = lane; i < n4; i += 32) {
                const int row = i / NF4;
                const int p   = i - row * NF4;
                const unsigned int sid = sstab[p];
                const float* gr = sgates[w][row];
                float4 v = sxw4[i];
                v.x *= gr[sid         & 255];
                v.y *= gr[(sid >> 8)  & 255];
                v.z *= gr[(sid >> 16) & 255];
                v.w *= gr[ sid >> 24       ];
                __stcs(&gout[i], v);
            }
        }
        // no drain: warp retires as soon as its stores issue
    }
}

extern "C" void kernel_launch(void* const* d_in, const int* in_sizes, int n_in,
                              void* d_out, int out_size)
{
    const float* x  = (const float*)d_in[0];
    const float* W1 = (const float*)d_in[1];
    const float* b1 = (const float*)d_in[2];
    const float* W2 = (const float*)d_in[3];
    const float* b2 = (const float*)d_in[4];
    float* out = (float*)d_out;

    const int B = in_sizes[0] / NFEAT;
    const int grid = (B + ROWS_BLK - 1) / ROWS_BLK;
    senet_kernel<<<grid, NTHREADS>>>(x, W1, b1, W2, b2, out, B);
}